// round 4
// baseline (speedup 1.0000x reference)
#include <cuda_runtime.h>
#include <cstdint>
#include <cstddef>

#define BB 256
#define SS 256
#define EE 128
#define HH 512
#define G4 2048
#define NEGINF (-1e9f)
#define NBLK 256
#define NTHR 256

// ---------------- static device scratch ----------------
__device__ float d_h[BB*HH];
__device__ float d_c[BB*HH];
__device__ float d_gates[BB*G4];
__device__ float d_encout[BB*SS*HH];
__device__ float d_glref[BB*SS*HH];
__device__ float d_ptref[BB*SS*HH];
__device__ float d_aq[BB*HH];
__device__ float d_ap[BB*HH];
__device__ float d_qv[BB*HH];
__device__ float d_decin[BB*EE];
__device__ unsigned char d_mask[BB*SS];
__device__ unsigned d_barcnt;
__device__ unsigned d_bargen;

__device__ __forceinline__ float sigm(float x){ return 1.0f/(1.0f+expf(-x)); }

// Threefry-2x32, 20 rounds (JAX constants)
__device__ __forceinline__ void tf2x32(uint32_t k0, uint32_t k1, uint32_t x0, uint32_t x1,
                                       uint32_t &o0, uint32_t &o1){
  uint32_t k2 = k0 ^ k1 ^ 0x1BD11BDAu;
#define TFR(r) { x0 += x1; x1 = (x1<<(r)) | (x1>>(32-(r))); x1 ^= x0; }
  x0 += k0; x1 += k1;
  TFR(13) TFR(15) TFR(26) TFR(6)
  x0 += k1; x1 += k2 + 1u;
  TFR(17) TFR(29) TFR(16) TFR(24)
  x0 += k2; x1 += k0 + 2u;
  TFR(13) TFR(15) TFR(26) TFR(6)
  x0 += k0; x1 += k1 + 3u;
  TFR(17) TFR(29) TFR(16) TFR(24)
  x0 += k1; x1 += k2 + 4u;
  TFR(13) TFR(15) TFR(26) TFR(6)
  x0 += k2; x1 += k0 + 5u;
#undef TFR
  o0 = x0; o1 = x1;
}

// ---------------- grid-wide barrier (all 256 blocks co-resident) ----------------
__device__ __forceinline__ void gridsync(){
  __syncthreads();
  if(threadIdx.x==0){
    unsigned g = *(volatile unsigned*)&d_bargen;
    __threadfence();
    unsigned prev = atomicAdd(&d_barcnt, 1u);
    if(prev == NBLK-1u){
      atomicExch(&d_barcnt, 0u);
      __threadfence();
      atomicExch(&d_bargen, g+1u);
    } else {
      while(*(volatile unsigned*)&d_bargen == g) __nanosleep(32);
      __threadfence();
    }
  }
  __syncthreads();
}

// ---------------- generic 64x64 tile GEMM: C[m0:,n0:] = A[M,512]@W^T + b ----------------
__device__ __forceinline__ void gemm_tile(const float* __restrict__ A, const float* __restrict__ W,
                                          const float* __restrict__ bias, float* __restrict__ C,
                                          long m0, int n0, float* As, float* Ws){
  const int tid  = threadIdx.x;
  const int arow = tid>>2, akq = tid&3;
  const int tx   = tid&15, ty  = tid>>4;
  float acc[4][4];
#pragma unroll
  for(int i=0;i<4;i++)
#pragma unroll
    for(int j=0;j<4;j++) acc[i][j]=0.0f;

  for(int k0=0;k0<HH;k0+=16){
    float4 a = *(const float4*)(A + (size_t)(m0+arow)*HH + k0 + akq*4);
    float4 w = *(const float4*)(W + (size_t)(n0+arow)*HH + k0 + akq*4);
    As[(akq*4+0)*68+arow]=a.x; As[(akq*4+1)*68+arow]=a.y; As[(akq*4+2)*68+arow]=a.z; As[(akq*4+3)*68+arow]=a.w;
    Ws[(akq*4+0)*68+arow]=w.x; Ws[(akq*4+1)*68+arow]=w.y; Ws[(akq*4+2)*68+arow]=w.z; Ws[(akq*4+3)*68+arow]=w.w;
    __syncthreads();
#pragma unroll
    for(int kk=0;kk<16;kk++){
      float4 av = *(const float4*)&As[kk*68+tx*4];
      float4 wv = *(const float4*)&Ws[kk*68+ty*4];
      acc[0][0]+=av.x*wv.x; acc[0][1]+=av.x*wv.y; acc[0][2]+=av.x*wv.z; acc[0][3]+=av.x*wv.w;
      acc[1][0]+=av.y*wv.x; acc[1][1]+=av.y*wv.y; acc[1][2]+=av.y*wv.z; acc[1][3]+=av.y*wv.w;
      acc[2][0]+=av.z*wv.x; acc[2][1]+=av.z*wv.y; acc[2][2]+=av.z*wv.z; acc[2][3]+=av.z*wv.w;
      acc[3][0]+=av.w*wv.x; acc[3][1]+=av.w*wv.y; acc[3][2]+=av.w*wv.z; acc[3][3]+=av.w*wv.w;
    }
    __syncthreads();
  }
  const int n = n0 + ty*4;
  float b0=bias[n+0], b1=bias[n+1], b2=bias[n+2], b3=bias[n+3];
#pragma unroll
  for(int i=0;i<4;i++){
    float4 o; o.x=acc[i][0]+b0; o.y=acc[i][1]+b1; o.z=acc[i][2]+b2; o.w=acc[i][3]+b3;
    *(float4*)(C + (size_t)(m0+tx*4+i)*HH + n) = o;
  }
}

// ---------------- gates tile: d_gates[64rows, 64cols] = h@Whh^T + x@Wih^T + b ----------------
__device__ __forceinline__ void gates_tile(const float* __restrict__ Whh, const float* __restrict__ Wih,
                                           const float* __restrict__ bias,
                                           const float* __restrict__ embedding,
                                           const int* __restrict__ inputs, int t,
                                           float* As, float* Ws, int* cities){
  const int tid  = threadIdx.x;
  const int n0   = (blockIdx.x & 31)*64, m0 = (blockIdx.x >> 5)*64;
  const int arow = tid>>2, akq = tid&3;
  const int tx   = tid&15, ty  = tid>>4;
  float acc[4][4];
#pragma unroll
  for(int i=0;i<4;i++)
#pragma unroll
    for(int j=0;j<4;j++) acc[i][j]=0.0f;

  // K1 = 512 : h @ Whh^T
  for(int k0=0;k0<HH;k0+=16){
    float4 a = *(const float4*)(d_h + (m0+arow)*HH + k0 + akq*4);
    float4 w = *(const float4*)(Whh + (n0+arow)*HH + k0 + akq*4);
    As[(akq*4+0)*68+arow]=a.x; As[(akq*4+1)*68+arow]=a.y; As[(akq*4+2)*68+arow]=a.z; As[(akq*4+3)*68+arow]=a.w;
    Ws[(akq*4+0)*68+arow]=w.x; Ws[(akq*4+1)*68+arow]=w.y; Ws[(akq*4+2)*68+arow]=w.z; Ws[(akq*4+3)*68+arow]=w.w;
    __syncthreads();
#pragma unroll
    for(int kk=0;kk<16;kk++){
      float4 av = *(const float4*)&As[kk*68+tx*4];
      float4 wv = *(const float4*)&Ws[kk*68+ty*4];
      acc[0][0]+=av.x*wv.x; acc[0][1]+=av.x*wv.y; acc[0][2]+=av.x*wv.z; acc[0][3]+=av.x*wv.w;
      acc[1][0]+=av.y*wv.x; acc[1][1]+=av.y*wv.y; acc[1][2]+=av.y*wv.z; acc[1][3]+=av.y*wv.w;
      acc[2][0]+=av.z*wv.x; acc[2][1]+=av.z*wv.y; acc[2][2]+=av.z*wv.z; acc[2][3]+=av.z*wv.w;
      acc[3][0]+=av.w*wv.x; acc[3][1]+=av.w*wv.y; acc[3][2]+=av.w*wv.z; acc[3][3]+=av.w*wv.w;
    }
    __syncthreads();
  }

  if(inputs){
    if(tid<64) cities[tid] = inputs[(m0+tid)*SS + t];
    __syncthreads();
  }

  // K2 = 128 : x @ Wih^T
  for(int k0=0;k0<EE;k0+=16){
    const float* xr = inputs ? (embedding + cities[arow]*EE) : (d_decin + (m0+arow)*EE);
    float4 a = *(const float4*)(xr + k0 + akq*4);
    float4 w = *(const float4*)(Wih + (n0+arow)*EE + k0 + akq*4);
    As[(akq*4+0)*68+arow]=a.x; As[(akq*4+1)*68+arow]=a.y; As[(akq*4+2)*68+arow]=a.z; As[(akq*4+3)*68+arow]=a.w;
    Ws[(akq*4+0)*68+arow]=w.x; Ws[(akq*4+1)*68+arow]=w.y; Ws[(akq*4+2)*68+arow]=w.z; Ws[(akq*4+3)*68+arow]=w.w;
    __syncthreads();
#pragma unroll
    for(int kk=0;kk<16;kk++){
      float4 av = *(const float4*)&As[kk*68+tx*4];
      float4 wv = *(const float4*)&Ws[kk*68+ty*4];
      acc[0][0]+=av.x*wv.x; acc[0][1]+=av.x*wv.y; acc[0][2]+=av.x*wv.z; acc[0][3]+=av.x*wv.w;
      acc[1][0]+=av.y*wv.x; acc[1][1]+=av.y*wv.y; acc[1][2]+=av.y*wv.z; acc[1][3]+=av.y*wv.w;
      acc[2][0]+=av.z*wv.x; acc[2][1]+=av.z*wv.y; acc[2][2]+=av.z*wv.z; acc[2][3]+=av.z*wv.w;
      acc[3][0]+=av.w*wv.x; acc[3][1]+=av.w*wv.y; acc[3][2]+=av.w*wv.z; acc[3][3]+=av.w*wv.w;
    }
    __syncthreads();
  }

  const int n = n0 + ty*4;
  float b0=bias[n+0], b1=bias[n+1], b2=bias[n+2], b3=bias[n+3];
#pragma unroll
  for(int i=0;i<4;i++){
    float4 o; o.x=acc[i][0]+b0; o.y=acc[i][1]+b1; o.z=acc[i][2]+b2; o.w=acc[i][3]+b3;
    *(float4*)(d_gates + (m0+tx*4+i)*G4 + n) = o;
  }
}

// ---------------- LSTM elementwise (grid-strided) ----------------
__device__ __forceinline__ void lstm_phase(int store_enc, int t){
  for(int idx = blockIdx.x*NTHR + threadIdx.x; idx < BB*HH; idx += NBLK*NTHR){
    int b = idx >> 9, j = idx & (HH-1);
    const float* g = d_gates + b*G4;
    float ig = sigm(g[j]);
    float fg = sigm(g[HH + j]);
    float gg = tanhf(g[2*HH + j]);
    float og = sigm(g[3*HH + j]);
    float cn = fg * d_c[idx] + ig * gg;
    float hn = og * tanhf(cn);
    d_c[idx] = cn; d_h[idx] = hn;
    if(store_enc) d_encout[(size_t)(b*SS + t)*HH + j] = hn;
  }
}

// ---------------- THE persistent mega-kernel ----------------
__global__ void __launch_bounds__(NTHR, 2)
pointer_net_kernel(const float* __restrict__ embedding,
                   const float* __restrict__ enc_Wih, const float* __restrict__ enc_Whh, const float* __restrict__ enc_b,
                   const float* __restrict__ dec_Wih, const float* __restrict__ dec_Whh, const float* __restrict__ dec_b,
                   const float* __restrict__ pt_Wq, const float* __restrict__ pt_bq,
                   const float* __restrict__ pt_Wref, const float* __restrict__ pt_bref, const float* __restrict__ pt_V,
                   const float* __restrict__ gl_Wq, const float* __restrict__ gl_bq,
                   const float* __restrict__ gl_Wref, const float* __restrict__ gl_bref, const float* __restrict__ gl_V,
                   const float* __restrict__ dec_start, const int* __restrict__ inputs,
                   float* __restrict__ out, int wr2)
{
  __shared__ __align__(16) float shPool[2176];
  __shared__ int shCities[64];
  __shared__ float s_scal[2];
  __shared__ int s_ptr;
  float* As = shPool;             // 16*68 = 1088
  float* Ws = shPool + 1088;      // 16*68 = 1088 (total 2176)
  const int tid = threadIdx.x;
  const int bx  = blockIdx.x;

  // ---- init ----
  for(int i = bx*NTHR + tid; i < BB*HH; i += NBLK*NTHR){
    d_h[i] = 0.0f; d_c[i] = 0.0f;
    if(i < BB*SS)  d_mask[i] = 0;
    if(i < BB*EE)  d_decin[i] = dec_start[i & (EE-1)];
  }
  gridsync();

  // ---- encoder ----
  for(int t=0;t<SS;t++){
    if(bx < 128) gates_tile(enc_Whh, enc_Wih, enc_b, embedding, inputs, t, As, Ws, shCities);
    gridsync();
    lstm_phase(1, t);
    gridsync();
  }

  // ---- ref precompute: glref & ptref ----
  for(int u = bx; u < 8192; u += NBLK)
    gemm_tile(d_encout, gl_Wref, gl_bref, d_glref, (long)(u>>3)*64, (u&7)*64, As, Ws);
  for(int u = bx; u < 8192; u += NBLK)
    gemm_tile(d_encout, pt_Wref, pt_bref, d_ptref, (long)(u>>3)*64, (u&7)*64, As, Ws);
  gridsync();

  // ---- decoder ----
  float* sq  = shPool;            // 512
  float* sV  = shPool + 512;      // 512
  float* sbf = shPool + 1024;     // 256 (logits)
  float* sp  = shPool + 1280;     // 256 (probs)
  float* red = shPool + 1536;     // 256
  int*  ridx = (int*)(shPool + 1792); // 256

  for(int t=0;t<SS;t++){
    if(bx < 128) gates_tile(dec_Whh, dec_Wih, dec_b, embedding, nullptr, t, As, Ws, shCities);
    gridsync();
    lstm_phase(0, t);
    gridsync();
    if(bx < 32) gemm_tile(d_h, gl_Wq, gl_bq, d_aq, (long)(bx>>3)*64, (bx&7)*64, As, Ws);
    gridsync();

    // ---- fused glimpse: attn logits + softmax + weighted sum (block per b) ----
    {
      const int b = bx;
      sq[tid] = d_aq[b*HH + tid];   sq[tid+256] = d_aq[b*HH + tid + 256];
      sV[tid] = gl_V[tid];          sV[tid+256] = gl_V[tid+256];
      __syncthreads();
      const int w = tid>>5, l = tid&31;
      for(int si=0; si<32; si++){
        int s = w*32 + si;
        float val = NEGINF;
        if(!d_mask[b*SS+s]){
          const float* r = d_glref + (size_t)(b*SS+s)*HH;
          float acc = 0.0f;
#pragma unroll
          for(int k=0;k<4;k++){
            int j = (k*32 + l)*4;
            float4 rv = *(const float4*)(r+j);
            acc += tanhf(sq[j+0]+rv.x)*sV[j+0] + tanhf(sq[j+1]+rv.y)*sV[j+1]
                 + tanhf(sq[j+2]+rv.z)*sV[j+2] + tanhf(sq[j+3]+rv.w)*sV[j+3];
          }
          for(int off=16; off; off>>=1) acc += __shfl_down_sync(0xffffffffu, acc, off);
          val = acc;
        }
        if(l==0) sbf[s] = val;
      }
      __syncthreads();
      // softmax
      float x = sbf[tid];
      red[tid]=x; __syncthreads();
      for(int off=128; off; off>>=1){ if(tid<off) red[tid]=fmaxf(red[tid],red[tid+off]); __syncthreads(); }
      if(tid==0) s_scal[0]=red[0]; __syncthreads();
      float e = expf(x - s_scal[0]);
      red[tid]=e; __syncthreads();
      for(int off=128; off; off>>=1){ if(tid<off) red[tid]+=red[tid+off]; __syncthreads(); }
      if(tid==0) s_scal[1]=red[0]; __syncthreads();
      sp[tid] = e / s_scal[1];
      __syncthreads();
      // weighted sum
      const float* base = d_glref + (size_t)b*SS*HH;
      for(int hh=0; hh<2; hh++){
        int h = tid + hh*256;
        float acc = 0.0f;
        for(int s=0;s<SS;s++){
          float ps = sp[s];
          if(ps != 0.0f) acc += ps * base[s*HH + h];
        }
        d_qv[b*HH + h] = acc;
      }
    }
    gridsync();
    if(bx < 32) gemm_tile(d_qv, pt_Wq, pt_bq, d_ap, (long)(bx>>3)*64, (bx&7)*64, As, Ws);
    gridsync();

    // ---- fused pointer: attn logits + gumbel sample + logp + mask + next emb ----
    {
      const int b = bx;
      sq[tid] = d_ap[b*HH + tid];   sq[tid+256] = d_ap[b*HH + tid + 256];
      sV[tid] = pt_V[tid];          sV[tid+256] = pt_V[tid+256];
      __syncthreads();
      const int w = tid>>5, l = tid&31;
      for(int si=0; si<32; si++){
        int s = w*32 + si;
        float val = NEGINF;
        if(!d_mask[b*SS+s]){
          const float* r = d_ptref + (size_t)(b*SS+s)*HH;
          float acc = 0.0f;
#pragma unroll
          for(int k=0;k<4;k++){
            int j = (k*32 + l)*4;
            float4 rv = *(const float4*)(r+j);
            acc += tanhf(sq[j+0]+rv.x)*sV[j+0] + tanhf(sq[j+1]+rv.y)*sV[j+1]
                 + tanhf(sq[j+2]+rv.z)*sV[j+2] + tanhf(sq[j+3]+rv.w)*sV[j+3];
          }
          for(int off=16; off; off>>=1) acc += __shfl_down_sync(0xffffffffu, acc, off);
          val = 10.0f * tanhf(acc);
        }
        if(l==0) sbf[s] = val;
      }
      __syncthreads();
      float lg = sbf[tid];
      // JAX partitionable threefry
      uint32_t a0,a1,o0,o1;
      tf2x32(0u, 1u, 0u, (uint32_t)t, a0, a1);
      tf2x32(a0, a1, 0u, (uint32_t)(b*SS+tid), o0, o1);
      uint32_t bits = o0 ^ o1;
      float u = __uint_as_float((bits>>9) | 0x3f800000u) - 1.0f;
      float gum = -logf(-logf(u + 1e-10f) + 1e-10f);
      float y = lg + gum;
      red[tid]=y; ridx[tid]=tid; __syncthreads();
      for(int off=128; off; off>>=1){
        if(tid<off){
          float v2=red[tid+off]; int i2=ridx[tid+off];
          if(v2>red[tid] || (v2==red[tid] && i2<ridx[tid])){ red[tid]=v2; ridx[tid]=i2; }
        }
        __syncthreads();
      }
      if(tid==0) s_ptr = ridx[0]; __syncthreads();
      red[tid]=lg; __syncthreads();
      for(int off=128; off; off>>=1){ if(tid<off) red[tid]=fmaxf(red[tid],red[tid+off]); __syncthreads(); }
      if(tid==0) s_scal[0]=red[0]; __syncthreads();
      red[tid]=expf(lg - s_scal[0]); __syncthreads();
      for(int off=128; off; off>>=1){ if(tid<off) red[tid]+=red[tid+off]; __syncthreads(); }
      if(tid==0) s_scal[1]=red[0]; __syncthreads();
      const int ptr = s_ptr;
      if(tid==0){
        float logp = sbf[ptr] - s_scal[0] - logf(s_scal[1]);
        out[b*SS + t] = (float)ptr;
        if(wr2) out[BB*SS + b*SS + t] = logp;
        d_mask[b*SS + ptr] = 1;
      }
      if(tid < EE){
        int city = inputs[b*SS + ptr];
        d_decin[b*EE + tid] = embedding[city*EE + tid];
      }
    }
    gridsync();
  }
}

extern "C" void kernel_launch(void* const* d_in, const int* in_sizes, int n_in,
                              void* d_out, int out_size) {
  const float* embedding = (const float*)d_in[0];
  const float* enc_Wih   = (const float*)d_in[1];
  const float* enc_Whh   = (const float*)d_in[2];
  const float* enc_b     = (const float*)d_in[3];
  const float* dec_Wih   = (const float*)d_in[4];
  const float* dec_Whh   = (const float*)d_in[5];
  const float* dec_b     = (const float*)d_in[6];
  const float* pt_Wq     = (const float*)d_in[7];
  const float* pt_bq     = (const float*)d_in[8];
  const float* pt_Wref   = (const float*)d_in[9];
  const float* pt_bref   = (const float*)d_in[10];
  const float* pt_V      = (const float*)d_in[11];
  const float* gl_Wq     = (const float*)d_in[12];
  const float* gl_bq     = (const float*)d_in[13];
  const float* gl_Wref   = (const float*)d_in[14];
  const float* gl_bref   = (const float*)d_in[15];
  const float* gl_V      = (const float*)d_in[16];
  const float* dec_start = (const float*)d_in[17];
  const int*   inputs    = (const int*)d_in[18];
  float* out = (float*)d_out;
  int wr2 = (out_size >= 2*BB*SS) ? 1 : 0;

  pointer_net_kernel<<<NBLK, NTHR>>>(embedding,
      enc_Wih, enc_Whh, enc_b, dec_Wih, dec_Whh, dec_b,
      pt_Wq, pt_bq, pt_Wref, pt_bref, pt_V,
      gl_Wq, gl_bq, gl_Wref, gl_bref, gl_V,
      dec_start, inputs, out, wr2);
}

// round 5
// speedup vs baseline: 1.2699x; 1.2699x over previous
#include <cuda_runtime.h>
#include <cstdint>
#include <cstddef>

#define BB 256
#define SS 256
#define EE 128
#define HH 512
#define NEGINF (-1e9f)
#define NBLK 256
#define NTHR 256

// ---------------- static device scratch ----------------
__device__ float d_h[BB*HH];
__device__ float d_c[BB*HH];
__device__ float d_encout[BB*SS*HH];
__device__ float d_glref[BB*SS*HH];
__device__ float d_ptref[BB*SS*HH];
__device__ float d_aq[BB*HH];
__device__ float d_ap[BB*HH];
__device__ float d_qv[BB*HH];
__device__ float d_decin[BB*EE];
__device__ int   d_alive[BB*SS];
__device__ unsigned d_barcnt;
__device__ unsigned d_bargen;

__device__ __forceinline__ float sigm(float x){ return 1.0f/(1.0f+expf(-x)); }

// Threefry-2x32, 20 rounds (JAX constants)
__device__ __forceinline__ void tf2x32(uint32_t k0, uint32_t k1, uint32_t x0, uint32_t x1,
                                       uint32_t &o0, uint32_t &o1){
  uint32_t k2 = k0 ^ k1 ^ 0x1BD11BDAu;
#define TFR(r) { x0 += x1; x1 = (x1<<(r)) | (x1>>(32-(r))); x1 ^= x0; }
  x0 += k0; x1 += k1;
  TFR(13) TFR(15) TFR(26) TFR(6)
  x0 += k1; x1 += k2 + 1u;
  TFR(17) TFR(29) TFR(16) TFR(24)
  x0 += k2; x1 += k0 + 2u;
  TFR(13) TFR(15) TFR(26) TFR(6)
  x0 += k0; x1 += k1 + 3u;
  TFR(17) TFR(29) TFR(16) TFR(24)
  x0 += k1; x1 += k2 + 4u;
  TFR(13) TFR(15) TFR(26) TFR(6)
  x0 += k2; x1 += k0 + 5u;
#undef TFR
  o0 = x0; o1 = x1;
}

// ---------------- grid-wide barrier (all 256 blocks co-resident) ----------------
__device__ __forceinline__ void gridsync(){
  __syncthreads();
  if(threadIdx.x==0){
    unsigned g = *(volatile unsigned*)&d_bargen;
    __threadfence();
    unsigned prev = atomicAdd(&d_barcnt, 1u);
    if(prev == NBLK-1u){
      atomicExch(&d_barcnt, 0u);
      __threadfence();
      atomicExch(&d_bargen, g+1u);
    } else {
      while(*(volatile unsigned*)&d_bargen == g) __nanosleep(32);
      __threadfence();
    }
  }
  __syncthreads();
}

// ---------------- 64x64 tile GEMM (refs): C = A[M,512]@W^T + b ----------------
__device__ __forceinline__ void gemm_tile(const float* __restrict__ A, const float* __restrict__ W,
                                          const float* __restrict__ bias, float* __restrict__ C,
                                          long m0, int n0, float* As, float* Ws){
  const int tid  = threadIdx.x;
  const int arow = tid>>2, akq = tid&3;
  const int tx   = tid&15, ty  = tid>>4;
  float acc[4][4];
#pragma unroll
  for(int i=0;i<4;i++)
#pragma unroll
    for(int j=0;j<4;j++) acc[i][j]=0.0f;

  for(int k0=0;k0<HH;k0+=16){
    float4 a = *(const float4*)(A + (size_t)(m0+arow)*HH + k0 + akq*4);
    float4 w = *(const float4*)(W + (size_t)(n0+arow)*HH + k0 + akq*4);
    As[(akq*4+0)*68+arow]=a.x; As[(akq*4+1)*68+arow]=a.y; As[(akq*4+2)*68+arow]=a.z; As[(akq*4+3)*68+arow]=a.w;
    Ws[(akq*4+0)*68+arow]=w.x; Ws[(akq*4+1)*68+arow]=w.y; Ws[(akq*4+2)*68+arow]=w.z; Ws[(akq*4+3)*68+arow]=w.w;
    __syncthreads();
#pragma unroll
    for(int kk=0;kk<16;kk++){
      float4 av = *(const float4*)&As[kk*68+tx*4];
      float4 wv = *(const float4*)&Ws[kk*68+ty*4];
      acc[0][0]+=av.x*wv.x; acc[0][1]+=av.x*wv.y; acc[0][2]+=av.x*wv.z; acc[0][3]+=av.x*wv.w;
      acc[1][0]+=av.y*wv.x; acc[1][1]+=av.y*wv.y; acc[1][2]+=av.y*wv.z; acc[1][3]+=av.y*wv.w;
      acc[2][0]+=av.z*wv.x; acc[2][1]+=av.z*wv.y; acc[2][2]+=av.z*wv.z; acc[2][3]+=av.z*wv.w;
      acc[3][0]+=av.w*wv.x; acc[3][1]+=av.w*wv.y; acc[3][2]+=av.w*wv.z; acc[3][3]+=av.w*wv.w;
    }
    __syncthreads();
  }
  const int n = n0 + ty*4;
  float b0=bias[n+0], b1=bias[n+1], b2=bias[n+2], b3=bias[n+3];
#pragma unroll
  for(int i=0;i<4;i++){
    float4 o; o.x=acc[i][0]+b0; o.y=acc[i][1]+b1; o.z=acc[i][2]+b2; o.w=acc[i][3]+b3;
    *(float4*)(C + (size_t)(m0+tx*4+i)*HH + n) = o;
  }
}

// ---------------- 32x32 tile GEMM (q projections): C[256,512] = A@W^T + b ----------------
__device__ __forceinline__ void gemm_tile32(const float* __restrict__ A, const float* __restrict__ W,
                                            const float* __restrict__ bias, float* __restrict__ C,
                                            int m0, int n0, float* As, float* Ws){
  const int tid = threadIdx.x;
  const int lr  = tid>>3, lk = (tid&7)*4;
  const int ty  = tid>>4, tx = tid&15;
  float a00=0.f,a01=0.f,a10=0.f,a11=0.f;
  for(int k0=0;k0<HH;k0+=32){
    float4 a = *(const float4*)(A + (m0+lr)*HH + k0 + lk);
    float4 w = *(const float4*)(W + (n0+lr)*HH + k0 + lk);
    As[(lk+0)*36+lr]=a.x; As[(lk+1)*36+lr]=a.y; As[(lk+2)*36+lr]=a.z; As[(lk+3)*36+lr]=a.w;
    Ws[(lk+0)*36+lr]=w.x; Ws[(lk+1)*36+lr]=w.y; Ws[(lk+2)*36+lr]=w.z; Ws[(lk+3)*36+lr]=w.w;
    __syncthreads();
#pragma unroll
    for(int kk=0;kk<32;kk++){
      float2 av = *(const float2*)&As[kk*36+ty*2];
      float2 wv = *(const float2*)&Ws[kk*36+tx*2];
      a00+=av.x*wv.x; a01+=av.x*wv.y; a10+=av.y*wv.x; a11+=av.y*wv.y;
    }
    __syncthreads();
  }
  int r0=m0+ty*2, c0=n0+tx*2;
  C[(size_t)r0*HH+c0]     = a00 + bias[c0];
  C[(size_t)r0*HH+c0+1]   = a01 + bias[c0+1];
  C[(size_t)(r0+1)*HH+c0]   = a10 + bias[c0];
  C[(size_t)(r0+1)*HH+c0+1] = a11 + bias[c0+1];
}

// ---------------- fused gates GEMM + LSTM epilogue ----------------
// col tile = [i(16) | f(16) | g(16) | o(16)] for j in [c*16, c*16+16)
__device__ __forceinline__ void gates_lstm_tile(const float* __restrict__ Whh, const float* __restrict__ Wih,
                                                const float* __restrict__ bias,
                                                const float* __restrict__ embedding,
                                                const int* __restrict__ inputs, int t, int store_enc,
                                                float* pool, int* cities){
  float* As = pool;
  float* Ws = pool + 1088;
  const int tid  = threadIdx.x;
  const int c    = blockIdx.x & 31;
  const int m0   = (blockIdx.x >> 5) * 64;
  const int arow = tid>>2, akq = tid&3;
  const int tx   = tid&15, ty  = tid>>4;
  const int wrow = ((arow>>4)*512) + c*16 + (arow&15);
  float acc[4][4];
#pragma unroll
  for(int i=0;i<4;i++)
#pragma unroll
    for(int j=0;j<4;j++) acc[i][j]=0.0f;

  // K1 = 512 : h @ Whh^T
  for(int k0=0;k0<HH;k0+=16){
    float4 a = *(const float4*)(d_h + (m0+arow)*HH + k0 + akq*4);
    float4 w = *(const float4*)(Whh + (size_t)wrow*HH + k0 + akq*4);
    As[(akq*4+0)*68+arow]=a.x; As[(akq*4+1)*68+arow]=a.y; As[(akq*4+2)*68+arow]=a.z; As[(akq*4+3)*68+arow]=a.w;
    Ws[(akq*4+0)*68+arow]=w.x; Ws[(akq*4+1)*68+arow]=w.y; Ws[(akq*4+2)*68+arow]=w.z; Ws[(akq*4+3)*68+arow]=w.w;
    __syncthreads();
#pragma unroll
    for(int kk=0;kk<16;kk++){
      float4 av = *(const float4*)&As[kk*68+tx*4];
      float4 wv = *(const float4*)&Ws[kk*68+ty*4];
      acc[0][0]+=av.x*wv.x; acc[0][1]+=av.x*wv.y; acc[0][2]+=av.x*wv.z; acc[0][3]+=av.x*wv.w;
      acc[1][0]+=av.y*wv.x; acc[1][1]+=av.y*wv.y; acc[1][2]+=av.y*wv.z; acc[1][3]+=av.y*wv.w;
      acc[2][0]+=av.z*wv.x; acc[2][1]+=av.z*wv.y; acc[2][2]+=av.z*wv.z; acc[2][3]+=av.z*wv.w;
      acc[3][0]+=av.w*wv.x; acc[3][1]+=av.w*wv.y; acc[3][2]+=av.w*wv.z; acc[3][3]+=av.w*wv.w;
    }
    __syncthreads();
  }

  if(inputs){
    if(tid<64) cities[tid] = inputs[(m0+tid)*SS + t];
    __syncthreads();
  }

  // K2 = 128 : x @ Wih^T
  for(int k0=0;k0<EE;k0+=16){
    const float* xr = inputs ? (embedding + cities[arow]*EE) : (d_decin + (m0+arow)*EE);
    float4 a = *(const float4*)(xr + k0 + akq*4);
    float4 w = *(const float4*)(Wih + (size_t)wrow*EE + k0 + akq*4);
    As[(akq*4+0)*68+arow]=a.x; As[(akq*4+1)*68+arow]=a.y; As[(akq*4+2)*68+arow]=a.z; As[(akq*4+3)*68+arow]=a.w;
    Ws[(akq*4+0)*68+arow]=w.x; Ws[(akq*4+1)*68+arow]=w.y; Ws[(akq*4+2)*68+arow]=w.z; Ws[(akq*4+3)*68+arow]=w.w;
    __syncthreads();
#pragma unroll
    for(int kk=0;kk<16;kk++){
      float4 av = *(const float4*)&As[kk*68+tx*4];
      float4 wv = *(const float4*)&Ws[kk*68+ty*4];
      acc[0][0]+=av.x*wv.x; acc[0][1]+=av.x*wv.y; acc[0][2]+=av.x*wv.z; acc[0][3]+=av.x*wv.w;
      acc[1][0]+=av.y*wv.x; acc[1][1]+=av.y*wv.y; acc[1][2]+=av.y*wv.z; acc[1][3]+=av.y*wv.w;
      acc[2][0]+=av.z*wv.x; acc[2][1]+=av.z*wv.y; acc[2][2]+=av.z*wv.z; acc[2][3]+=av.z*wv.w;
      acc[3][0]+=av.w*wv.x; acc[3][1]+=av.w*wv.y; acc[3][2]+=av.w*wv.z; acc[3][3]+=av.w*wv.w;
    }
    __syncthreads();
  }

  // write gate tile (with bias) into smem (aliases As/Ws — safe after final sync)
  float* T = pool;  // 64 x 65
#pragma unroll
  for(int i=0;i<4;i++){
#pragma unroll
    for(int j2=0;j2<4;j2++){
      int cc = ty*4+j2;
      T[(tx*4+i)*65 + cc] = acc[i][j2] + bias[((cc>>4)*512) + c*16 + (cc&15)];
    }
  }
  __syncthreads();

  // LSTM for the 64 rows x 16 j cells this block owns
#pragma unroll
  for(int u=0;u<4;u++){
    int cell = tid + u*256;
    int r = cell>>4, jj = cell&15;
    float ig = sigm(T[r*65+jj]);
    float fg = sigm(T[r*65+16+jj]);
    float gg = tanhf(T[r*65+32+jj]);
    float og = sigm(T[r*65+48+jj]);
    int b = m0 + r, j = c*16 + jj;
    float cn = fg * d_c[b*HH+j] + ig * gg;
    float hn = og * tanhf(cn);
    d_c[b*HH+j] = cn; d_h[b*HH+j] = hn;
    if(store_enc) d_encout[((size_t)b*SS + t)*HH + j] = hn;
  }
}

// ---------------- THE persistent mega-kernel ----------------
__global__ void __launch_bounds__(NTHR, 2)
pointer_net_kernel(const float* __restrict__ embedding,
                   const float* __restrict__ enc_Wih, const float* __restrict__ enc_Whh, const float* __restrict__ enc_b,
                   const float* __restrict__ dec_Wih, const float* __restrict__ dec_Whh, const float* __restrict__ dec_b,
                   const float* __restrict__ pt_Wq, const float* __restrict__ pt_bq,
                   const float* __restrict__ pt_Wref, const float* __restrict__ pt_bref, const float* __restrict__ pt_V,
                   const float* __restrict__ gl_Wq, const float* __restrict__ gl_bq,
                   const float* __restrict__ gl_Wref, const float* __restrict__ gl_bref, const float* __restrict__ gl_V,
                   const float* __restrict__ dec_start, const int* __restrict__ inputs,
                   float* __restrict__ out, int wr2)
{
  __shared__ __align__(16) float shPool[4160];
  __shared__ int shCities[64];
  __shared__ unsigned s_wm[8];
  __shared__ float s_scal[2];
  __shared__ int s_ptr;
  const int tid = threadIdx.x;
  const int bx  = blockIdx.x;

  // ---- init ----
  for(int i = bx*NTHR + tid; i < BB*HH; i += NBLK*NTHR){
    d_h[i] = 0.0f; d_c[i] = 0.0f;
    if(i < BB*SS)  d_alive[i] = i & (SS-1);
    if(i < BB*EE)  d_decin[i] = dec_start[i & (EE-1)];
  }
  gridsync();

  // ---- encoder (fused gates+lstm, 1 barrier/step) ----
  for(int t=0;t<SS;t++){
    if(bx < 128) gates_lstm_tile(enc_Whh, enc_Wih, enc_b, embedding, inputs, t, 1, shPool, shCities);
    gridsync();
  }

  // ---- ref precompute: glref & ptref ----
  for(int u = bx; u < 8192; u += NBLK)
    gemm_tile(d_encout, gl_Wref, gl_bref, d_glref, (long)(u>>3)*64, (u&7)*64, shPool, shPool+1088);
  for(int u = bx; u < 8192; u += NBLK)
    gemm_tile(d_encout, pt_Wref, pt_bref, d_ptref, (long)(u>>3)*64, (u&7)*64, shPool, shPool+1088);
  gridsync();

  // ---- decoder ----
  float* sq  = shPool;                 // 512
  float* sV  = shPool + 512;           // 512
  float* sbf = shPool + 1024;          // 256 (logits, s-indexed)
  float* sp  = shPool + 1280;          // 256 (probs, s-indexed)
  float* red = shPool + 1536;          // 256
  int*  ridx = (int*)(shPool + 1792);  // 256

  for(int t=0;t<SS;t++){
    const int n = SS - t;              // alive count this step
    if(bx < 128) gates_lstm_tile(dec_Whh, dec_Wih, dec_b, embedding, nullptr, t, 0, shPool, shCities);
    gridsync();
    if(bx < 128) gemm_tile32(d_h, gl_Wq, gl_bq, d_aq, (bx>>4)*32, (bx&15)*32, shPool, shPool+1152);
    gridsync();

    // ---- fused glimpse: logits (alive-compacted, 4-row ILP) + softmax + wsum ----
    {
      const int b = bx;
      const int* alive = d_alive + b*SS;
      sq[tid] = d_aq[b*HH + tid];   sq[tid+256] = d_aq[b*HH + tid + 256];
      sV[tid] = gl_V[tid];          sV[tid+256] = gl_V[tid+256];
      sbf[tid] = NEGINF;
      __syncthreads();
      const int w = tid>>5, l = tid&31;
      for(int base = w*4; base < n; base += 32){
        int r0 = alive[base];
        int r1 = (base+1<n) ? alive[base+1] : r0;
        int r2 = (base+2<n) ? alive[base+2] : r0;
        int r3 = (base+3<n) ? alive[base+3] : r0;
        const float* p0 = d_glref + ((size_t)b*SS + r0)*HH;
        const float* p1 = d_glref + ((size_t)b*SS + r1)*HH;
        const float* p2 = d_glref + ((size_t)b*SS + r2)*HH;
        const float* p3 = d_glref + ((size_t)b*SS + r3)*HH;
        float4 v0[4], v1[4], v2[4], v3[4];
#pragma unroll
        for(int k=0;k<4;k++){
          int j = (k*32 + l)*4;
          v0[k] = *(const float4*)(p0+j);
          v1[k] = *(const float4*)(p1+j);
          v2[k] = *(const float4*)(p2+j);
          v3[k] = *(const float4*)(p3+j);
        }
        float a0=0.f,a1=0.f,a2=0.f,a3=0.f;
#pragma unroll
        for(int k=0;k<4;k++){
          int j = (k*32 + l)*4;
          a0 += tanhf(sq[j+0]+v0[k].x)*sV[j+0] + tanhf(sq[j+1]+v0[k].y)*sV[j+1]
              + tanhf(sq[j+2]+v0[k].z)*sV[j+2] + tanhf(sq[j+3]+v0[k].w)*sV[j+3];
          a1 += tanhf(sq[j+0]+v1[k].x)*sV[j+0] + tanhf(sq[j+1]+v1[k].y)*sV[j+1]
              + tanhf(sq[j+2]+v1[k].z)*sV[j+2] + tanhf(sq[j+3]+v1[k].w)*sV[j+3];
          a2 += tanhf(sq[j+0]+v2[k].x)*sV[j+0] + tanhf(sq[j+1]+v2[k].y)*sV[j+1]
              + tanhf(sq[j+2]+v2[k].z)*sV[j+2] + tanhf(sq[j+3]+v2[k].w)*sV[j+3];
          a3 += tanhf(sq[j+0]+v3[k].x)*sV[j+0] + tanhf(sq[j+1]+v3[k].y)*sV[j+1]
              + tanhf(sq[j+2]+v3[k].z)*sV[j+2] + tanhf(sq[j+3]+v3[k].w)*sV[j+3];
        }
        for(int off=16; off; off>>=1){
          a0 += __shfl_down_sync(0xffffffffu, a0, off);
          a1 += __shfl_down_sync(0xffffffffu, a1, off);
          a2 += __shfl_down_sync(0xffffffffu, a2, off);
          a3 += __shfl_down_sync(0xffffffffu, a3, off);
        }
        if(l==0){
          sbf[r0] = a0;
          if(base+1<n) sbf[r1] = a1;
          if(base+2<n) sbf[r2] = a2;
          if(base+3<n) sbf[r3] = a3;
        }
      }
      __syncthreads();
      // softmax (identical to R3)
      float x = sbf[tid];
      red[tid]=x; __syncthreads();
      for(int off=128; off; off>>=1){ if(tid<off) red[tid]=fmaxf(red[tid],red[tid+off]); __syncthreads(); }
      if(tid==0) s_scal[0]=red[0]; __syncthreads();
      float e = expf(x - s_scal[0]);
      red[tid]=e; __syncthreads();
      for(int off=128; off; off>>=1){ if(tid<off) red[tid]+=red[tid+off]; __syncthreads(); }
      if(tid==0) s_scal[1]=red[0]; __syncthreads();
      sp[tid] = e / s_scal[1];
      __syncthreads();
      // weighted sum over alive rows, ascending order (bitwise same as skip-zeros)
      const float* basep = d_glref + (size_t)b*SS*HH;
#pragma unroll
      for(int hh=0; hh<2; hh++){
        int h = tid + hh*256;
        float acc = 0.0f;
        int k2 = 0;
        for(; k2+3 < n; k2+=4){
          int s0=alive[k2], s1=alive[k2+1], s2=alive[k2+2], s3=alive[k2+3];
          float x0=basep[s0*HH+h], x1=basep[s1*HH+h], x2=basep[s2*HH+h], x3=basep[s3*HH+h];
          acc += sp[s0]*x0; acc += sp[s1]*x1; acc += sp[s2]*x2; acc += sp[s3]*x3;
        }
        for(; k2<n; k2++){ int s=alive[k2]; acc += sp[s]*basep[s*HH+h]; }
        d_qv[b*HH + h] = acc;
      }
    }
    gridsync();
    if(bx < 128) gemm_tile32(d_qv, pt_Wq, pt_bq, d_ap, (bx>>4)*32, (bx&15)*32, shPool, shPool+1152);
    gridsync();

    // ---- fused pointer: logits (compacted, ILP) + gumbel sample + logp + alive rebuild ----
    {
      const int b = bx;
      const int* alive = d_alive + b*SS;
      sq[tid] = d_ap[b*HH + tid];   sq[tid+256] = d_ap[b*HH + tid + 256];
      sV[tid] = pt_V[tid];          sV[tid+256] = pt_V[tid+256];
      sbf[tid] = NEGINF;
      __syncthreads();
      const int w = tid>>5, l = tid&31;
      for(int base = w*4; base < n; base += 32){
        int r0 = alive[base];
        int r1 = (base+1<n) ? alive[base+1] : r0;
        int r2 = (base+2<n) ? alive[base+2] : r0;
        int r3 = (base+3<n) ? alive[base+3] : r0;
        const float* p0 = d_ptref + ((size_t)b*SS + r0)*HH;
        const float* p1 = d_ptref + ((size_t)b*SS + r1)*HH;
        const float* p2 = d_ptref + ((size_t)b*SS + r2)*HH;
        const float* p3 = d_ptref + ((size_t)b*SS + r3)*HH;
        float4 v0[4], v1[4], v2[4], v3[4];
#pragma unroll
        for(int k=0;k<4;k++){
          int j = (k*32 + l)*4;
          v0[k] = *(const float4*)(p0+j);
          v1[k] = *(const float4*)(p1+j);
          v2[k] = *(const float4*)(p2+j);
          v3[k] = *(const float4*)(p3+j);
        }
        float a0=0.f,a1=0.f,a2=0.f,a3=0.f;
#pragma unroll
        for(int k=0;k<4;k++){
          int j = (k*32 + l)*4;
          a0 += tanhf(sq[j+0]+v0[k].x)*sV[j+0] + tanhf(sq[j+1]+v0[k].y)*sV[j+1]
              + tanhf(sq[j+2]+v0[k].z)*sV[j+2] + tanhf(sq[j+3]+v0[k].w)*sV[j+3];
          a1 += tanhf(sq[j+0]+v1[k].x)*sV[j+0] + tanhf(sq[j+1]+v1[k].y)*sV[j+1]
              + tanhf(sq[j+2]+v1[k].z)*sV[j+2] + tanhf(sq[j+3]+v1[k].w)*sV[j+3];
          a2 += tanhf(sq[j+0]+v2[k].x)*sV[j+0] + tanhf(sq[j+1]+v2[k].y)*sV[j+1]
              + tanhf(sq[j+2]+v2[k].z)*sV[j+2] + tanhf(sq[j+3]+v2[k].w)*sV[j+3];
          a3 += tanhf(sq[j+0]+v3[k].x)*sV[j+0] + tanhf(sq[j+1]+v3[k].y)*sV[j+1]
              + tanhf(sq[j+2]+v3[k].z)*sV[j+2] + tanhf(sq[j+3]+v3[k].w)*sV[j+3];
        }
        for(int off=16; off; off>>=1){
          a0 += __shfl_down_sync(0xffffffffu, a0, off);
          a1 += __shfl_down_sync(0xffffffffu, a1, off);
          a2 += __shfl_down_sync(0xffffffffu, a2, off);
          a3 += __shfl_down_sync(0xffffffffu, a3, off);
        }
        if(l==0){
          sbf[r0] = 10.0f*tanhf(a0);
          if(base+1<n) sbf[r1] = 10.0f*tanhf(a1);
          if(base+2<n) sbf[r2] = 10.0f*tanhf(a2);
          if(base+3<n) sbf[r3] = 10.0f*tanhf(a3);
        }
      }
      __syncthreads();
      float lg = sbf[tid];
      // JAX partitionable threefry
      uint32_t a0u,a1u,o0,o1;
      tf2x32(0u, 1u, 0u, (uint32_t)t, a0u, a1u);
      tf2x32(a0u, a1u, 0u, (uint32_t)(b*SS+tid), o0, o1);
      uint32_t bits = o0 ^ o1;
      float u = __uint_as_float((bits>>9) | 0x3f800000u) - 1.0f;
      float gum = -logf(-logf(u + 1e-10f) + 1e-10f);
      float y = lg + gum;
      red[tid]=y; ridx[tid]=tid; __syncthreads();
      for(int off=128; off; off>>=1){
        if(tid<off){
          float v2f=red[tid+off]; int i2=ridx[tid+off];
          if(v2f>red[tid] || (v2f==red[tid] && i2<ridx[tid])){ red[tid]=v2f; ridx[tid]=i2; }
        }
        __syncthreads();
      }
      if(tid==0) s_ptr = ridx[0]; __syncthreads();
      red[tid]=lg; __syncthreads();
      for(int off=128; off; off>>=1){ if(tid<off) red[tid]=fmaxf(red[tid],red[tid+off]); __syncthreads(); }
      if(tid==0) s_scal[0]=red[0]; __syncthreads();
      red[tid]=expf(lg - s_scal[0]); __syncthreads();
      for(int off=128; off; off>>=1){ if(tid<off) red[tid]+=red[tid+off]; __syncthreads(); }
      if(tid==0) s_scal[1]=red[0]; __syncthreads();
      const int ptr = s_ptr;
      if(tid==0){
        float logp = sbf[ptr] - s_scal[0] - logf(s_scal[1]);
        out[b*SS + t] = (float)ptr;
        if(wr2) out[BB*SS + b*SS + t] = logp;
      }
      // rebuild alive list (exclude chosen ptr; previously-masked have sbf == NEGINF)
      unsigned aliveb = (sbf[tid] > -1e8f) && (tid != ptr);
      unsigned wm = __ballot_sync(0xffffffffu, aliveb);
      if(l==0) s_wm[w] = wm;
      __syncthreads();
      int rank = __popc(wm & ((l==31)?0x7fffffffu:((1u<<l)-1u)));
      for(int ww=0; ww<w; ww++) rank += __popc(s_wm[ww]);
      if(aliveb) d_alive[b*SS + rank] = tid;
      if(tid < EE){
        int city = inputs[b*SS + ptr];
        d_decin[b*EE + tid] = embedding[city*EE + tid];
      }
    }
    gridsync();
  }
}

extern "C" void kernel_launch(void* const* d_in, const int* in_sizes, int n_in,
                              void* d_out, int out_size) {
  const float* embedding = (const float*)d_in[0];
  const float* enc_Wih   = (const float*)d_in[1];
  const float* enc_Whh   = (const float*)d_in[2];
  const float* enc_b     = (const float*)d_in[3];
  const float* dec_Wih   = (const float*)d_in[4];
  const float* dec_Whh   = (const float*)d_in[5];
  const float* dec_b     = (const float*)d_in[6];
  const float* pt_Wq     = (const float*)d_in[7];
  const float* pt_bq     = (const float*)d_in[8];
  const float* pt_Wref   = (const float*)d_in[9];
  const float* pt_bref   = (const float*)d_in[10];
  const float* pt_V      = (const float*)d_in[11];
  const float* gl_Wq     = (const float*)d_in[12];
  const float* gl_bq     = (const float*)d_in[13];
  const float* gl_Wref   = (const float*)d_in[14];
  const float* gl_bref   = (const float*)d_in[15];
  const float* gl_V      = (const float*)d_in[16];
  const float* dec_start = (const float*)d_in[17];
  const int*   inputs    = (const int*)d_in[18];
  float* out = (float*)d_out;
  int wr2 = (out_size >= 2*BB*SS) ? 1 : 0;

  pointer_net_kernel<<<NBLK, NTHR>>>(embedding,
      enc_Wih, enc_Whh, enc_b, dec_Wih, dec_Whh, dec_b,
      pt_Wq, pt_bq, pt_Wref, pt_bref, pt_V,
      gl_Wq, gl_bq, gl_Wref, gl_bref, gl_V,
      dec_start, inputs, out, wr2);
}

// round 6
// speedup vs baseline: 1.3297x; 1.0471x over previous
#include <cuda_runtime.h>
#include <cstdint>
#include <cstddef>

#define BB 256
#define SS 256
#define EE 128
#define HH 512
#define NEGINF (-1e9f)
#define NBLK 256
#define NTHR 256

// ---------------- static device scratch ----------------
__device__ float d_h[BB*HH];
__device__ float d_c[BB*HH];
__device__ float d_encout[BB*SS*HH];
__device__ float d_glref[BB*SS*HH];
__device__ float d_ptref[BB*SS*HH];
__device__ float d_aq[BB*HH];
__device__ float d_ap[BB*HH];
__device__ float d_qv[BB*HH];
__device__ float d_decin[BB*EE];
__device__ int   d_alive[BB*SS];
__device__ unsigned d_barcnt;
__device__ unsigned d_bargen;

__device__ __forceinline__ float sigm(float x){ return 1.0f/(1.0f+expf(-x)); }

__device__ __forceinline__ uint32_t s2u(const void* p){
  uint32_t r;
  asm("{ .reg .u64 t; cvta.to.shared.u64 t, %1; cvt.u32.u64 %0, t; }" : "=r"(r) : "l"(p));
  return r;
}

#define MBINIT(a,c)  asm volatile("mbarrier.init.shared.b64 [%0], %1;" :: "r"(a), "r"(c) : "memory")
#define MBINVAL(a)   asm volatile("mbarrier.inval.shared.b64 [%0];" :: "r"(a) : "memory")
#define MBEXPECT(a,b) asm volatile("mbarrier.arrive.expect_tx.shared.b64 _, [%0], %1;" :: "r"(a), "r"(b) : "memory")
#define BULK_G2S(dst,src,bytes,mbar) \
  asm volatile("cp.async.bulk.shared::cluster.global.mbarrier::complete_tx::bytes [%0], [%1], %2, [%3];" \
               :: "r"(dst), "l"(src), "r"(bytes), "r"(mbar) : "memory")

__device__ __forceinline__ void mbwait(uint32_t a, uint32_t ph){
  uint32_t done;
  asm volatile("{ .reg .pred p; mbarrier.try_wait.parity.acquire.cta.shared::cta.b64 p, [%1], %2; selp.b32 %0,1,0,p; }"
               : "=r"(done) : "r"(a), "r"(ph) : "memory");
  while(!done){
    asm volatile("{ .reg .pred p; mbarrier.try_wait.parity.acquire.cta.shared::cta.b64 p, [%1], %2, 0x989680; selp.b32 %0,1,0,p; }"
                 : "=r"(done) : "r"(a), "r"(ph) : "memory");
  }
}

// Threefry-2x32, 20 rounds (JAX constants)
__device__ __forceinline__ void tf2x32(uint32_t k0, uint32_t k1, uint32_t x0, uint32_t x1,
                                       uint32_t &o0, uint32_t &o1){
  uint32_t k2 = k0 ^ k1 ^ 0x1BD11BDAu;
#define TFR(r) { x0 += x1; x1 = (x1<<(r)) | (x1>>(32-(r))); x1 ^= x0; }
  x0 += k0; x1 += k1;
  TFR(13) TFR(15) TFR(26) TFR(6)
  x0 += k1; x1 += k2 + 1u;
  TFR(17) TFR(29) TFR(16) TFR(24)
  x0 += k2; x1 += k0 + 2u;
  TFR(13) TFR(15) TFR(26) TFR(6)
  x0 += k0; x1 += k1 + 3u;
  TFR(17) TFR(29) TFR(16) TFR(24)
  x0 += k1; x1 += k2 + 4u;
  TFR(13) TFR(15) TFR(26) TFR(6)
  x0 += k2; x1 += k0 + 5u;
#undef TFR
  o0 = x0; o1 = x1;
}

// ---------------- grid-wide barrier ----------------
__device__ __forceinline__ void gridsync(){
  __syncthreads();
  if(threadIdx.x==0){
    unsigned g = *(volatile unsigned*)&d_bargen;
    __threadfence();
    unsigned prev = atomicAdd(&d_barcnt, 1u);
    if(prev == NBLK-1u){
      atomicExch(&d_barcnt, 0u);
      __threadfence();
      atomicExch(&d_bargen, g+1u);
    } else {
      while(*(volatile unsigned*)&d_bargen == g) __nanosleep(32);
      __threadfence();
    }
  }
  __syncthreads();
}

// ---------------- 64x64 tile GEMM (refs), prefetched ----------------
__device__ __forceinline__ void gemm_tile(const float* __restrict__ A, const float* __restrict__ W,
                                          const float* __restrict__ bias, float* __restrict__ C,
                                          long m0, int n0, float* As, float* Ws){
  const int tid  = threadIdx.x;
  const int arow = tid>>2, akq = tid&3;
  const int tx   = tid&15, ty  = tid>>4;
  float acc[4][4];
#pragma unroll
  for(int i=0;i<4;i++)
#pragma unroll
    for(int j=0;j<4;j++) acc[i][j]=0.0f;

  float4 a = *(const float4*)(A + (size_t)(m0+arow)*HH + akq*4);
  float4 w = *(const float4*)(W + (size_t)(n0+arow)*HH + akq*4);
  for(int k0=0;k0<HH;k0+=16){
    As[(akq*4+0)*68+arow]=a.x; As[(akq*4+1)*68+arow]=a.y; As[(akq*4+2)*68+arow]=a.z; As[(akq*4+3)*68+arow]=a.w;
    Ws[(akq*4+0)*68+arow]=w.x; Ws[(akq*4+1)*68+arow]=w.y; Ws[(akq*4+2)*68+arow]=w.z; Ws[(akq*4+3)*68+arow]=w.w;
    __syncthreads();
    if(k0+16<HH){
      a = *(const float4*)(A + (size_t)(m0+arow)*HH + k0+16 + akq*4);
      w = *(const float4*)(W + (size_t)(n0+arow)*HH + k0+16 + akq*4);
    }
#pragma unroll
    for(int kk=0;kk<16;kk++){
      float4 av = *(const float4*)&As[kk*68+tx*4];
      float4 wv = *(const float4*)&Ws[kk*68+ty*4];
      acc[0][0]+=av.x*wv.x; acc[0][1]+=av.x*wv.y; acc[0][2]+=av.x*wv.z; acc[0][3]+=av.x*wv.w;
      acc[1][0]+=av.y*wv.x; acc[1][1]+=av.y*wv.y; acc[1][2]+=av.y*wv.z; acc[1][3]+=av.y*wv.w;
      acc[2][0]+=av.z*wv.x; acc[2][1]+=av.z*wv.y; acc[2][2]+=av.z*wv.z; acc[2][3]+=av.z*wv.w;
      acc[3][0]+=av.w*wv.x; acc[3][1]+=av.w*wv.y; acc[3][2]+=av.w*wv.z; acc[3][3]+=av.w*wv.w;
    }
    __syncthreads();
  }
  const int n = n0 + ty*4;
  float b0=bias[n+0], b1=bias[n+1], b2=bias[n+2], b3=bias[n+3];
#pragma unroll
  for(int i=0;i<4;i++){
    float4 o; o.x=acc[i][0]+b0; o.y=acc[i][1]+b1; o.z=acc[i][2]+b2; o.w=acc[i][3]+b3;
    *(float4*)(C + (size_t)(m0+tx*4+i)*HH + n) = o;
  }
}

// ---------------- 32x32 tile GEMM (q projections) ----------------
__device__ __forceinline__ void gemm_tile32(const float* __restrict__ A, const float* __restrict__ W,
                                            const float* __restrict__ bias, float* __restrict__ C,
                                            int m0, int n0, float* As, float* Ws){
  const int tid = threadIdx.x;
  const int lr  = tid>>3, lk = (tid&7)*4;
  const int ty  = tid>>4, tx = tid&15;
  float a00=0.f,a01=0.f,a10=0.f,a11=0.f;
  for(int k0=0;k0<HH;k0+=32){
    float4 a = *(const float4*)(A + (m0+lr)*HH + k0 + lk);
    float4 w = *(const float4*)(W + (n0+lr)*HH + k0 + lk);
    As[(lk+0)*36+lr]=a.x; As[(lk+1)*36+lr]=a.y; As[(lk+2)*36+lr]=a.z; As[(lk+3)*36+lr]=a.w;
    Ws[(lk+0)*36+lr]=w.x; Ws[(lk+1)*36+lr]=w.y; Ws[(lk+2)*36+lr]=w.z; Ws[(lk+3)*36+lr]=w.w;
    __syncthreads();
#pragma unroll
    for(int kk=0;kk<32;kk++){
      float2 av = *(const float2*)&As[kk*36+ty*2];
      float2 wv = *(const float2*)&Ws[kk*36+tx*2];
      a00+=av.x*wv.x; a01+=av.x*wv.y; a10+=av.y*wv.x; a11+=av.y*wv.y;
    }
    __syncthreads();
  }
  int r0=m0+ty*2, c0=n0+tx*2;
  C[(size_t)r0*HH+c0]     = a00 + bias[c0];
  C[(size_t)r0*HH+c0+1]   = a01 + bias[c0+1];
  C[(size_t)(r0+1)*HH+c0]   = a10 + bias[c0];
  C[(size_t)(r0+1)*HH+c0+1] = a11 + bias[c0+1];
}

// ---------------- fused gates GEMM + LSTM epilogue (prefetched) ----------------
__device__ __forceinline__ void gates_lstm_tile(const float* __restrict__ Whh, const float* __restrict__ Wih,
                                                const float* __restrict__ bias,
                                                const float* __restrict__ embedding,
                                                const int* __restrict__ inputs, int t, int store_enc,
                                                float* pool, int* cities){
  float* As = pool;
  float* Ws = pool + 1088;
  const int tid  = threadIdx.x;
  const int c    = blockIdx.x & 31;
  const int m0   = (blockIdx.x >> 5) * 64;
  const int arow = tid>>2, akq = tid&3;
  const int tx   = tid&15, ty  = tid>>4;
  const int wrow = ((arow>>4)*512) + c*16 + (arow&15);
  float acc[4][4];
#pragma unroll
  for(int i=0;i<4;i++)
#pragma unroll
    for(int j=0;j<4;j++) acc[i][j]=0.0f;

  // K1 = 512 : h @ Whh^T (prefetched)
  {
    float4 a = *(const float4*)(d_h + (m0+arow)*HH + akq*4);
    float4 w = *(const float4*)(Whh + (size_t)wrow*HH + akq*4);
    for(int k0=0;k0<HH;k0+=16){
      As[(akq*4+0)*68+arow]=a.x; As[(akq*4+1)*68+arow]=a.y; As[(akq*4+2)*68+arow]=a.z; As[(akq*4+3)*68+arow]=a.w;
      Ws[(akq*4+0)*68+arow]=w.x; Ws[(akq*4+1)*68+arow]=w.y; Ws[(akq*4+2)*68+arow]=w.z; Ws[(akq*4+3)*68+arow]=w.w;
      __syncthreads();
      if(k0+16<HH){
        a = *(const float4*)(d_h + (m0+arow)*HH + k0+16 + akq*4);
        w = *(const float4*)(Whh + (size_t)wrow*HH + k0+16 + akq*4);
      }
#pragma unroll
      for(int kk=0;kk<16;kk++){
        float4 av = *(const float4*)&As[kk*68+tx*4];
        float4 wv = *(const float4*)&Ws[kk*68+ty*4];
        acc[0][0]+=av.x*wv.x; acc[0][1]+=av.x*wv.y; acc[0][2]+=av.x*wv.z; acc[0][3]+=av.x*wv.w;
        acc[1][0]+=av.y*wv.x; acc[1][1]+=av.y*wv.y; acc[1][2]+=av.y*wv.z; acc[1][3]+=av.y*wv.w;
        acc[2][0]+=av.z*wv.x; acc[2][1]+=av.z*wv.y; acc[2][2]+=av.z*wv.z; acc[2][3]+=av.z*wv.w;
        acc[3][0]+=av.w*wv.x; acc[3][1]+=av.w*wv.y; acc[3][2]+=av.w*wv.z; acc[3][3]+=av.w*wv.w;
      }
      __syncthreads();
    }
  }

  if(inputs){
    if(tid<64) cities[tid] = inputs[(m0+tid)*SS + t];
    __syncthreads();
  }

  // K2 = 128 : x @ Wih^T
  for(int k0=0;k0<EE;k0+=16){
    const float* xr = inputs ? (embedding + cities[arow]*EE) : (d_decin + (m0+arow)*EE);
    float4 a = *(const float4*)(xr + k0 + akq*4);
    float4 w = *(const float4*)(Wih + (size_t)wrow*EE + k0 + akq*4);
    As[(akq*4+0)*68+arow]=a.x; As[(akq*4+1)*68+arow]=a.y; As[(akq*4+2)*68+arow]=a.z; As[(akq*4+3)*68+arow]=a.w;
    Ws[(akq*4+0)*68+arow]=w.x; Ws[(akq*4+1)*68+arow]=w.y; Ws[(akq*4+2)*68+arow]=w.z; Ws[(akq*4+3)*68+arow]=w.w;
    __syncthreads();
#pragma unroll
    for(int kk=0;kk<16;kk++){
      float4 av = *(const float4*)&As[kk*68+tx*4];
      float4 wv = *(const float4*)&Ws[kk*68+ty*4];
      acc[0][0]+=av.x*wv.x; acc[0][1]+=av.x*wv.y; acc[0][2]+=av.x*wv.z; acc[0][3]+=av.x*wv.w;
      acc[1][0]+=av.y*wv.x; acc[1][1]+=av.y*wv.y; acc[1][2]+=av.y*wv.z; acc[1][3]+=av.y*wv.w;
      acc[2][0]+=av.z*wv.x; acc[2][1]+=av.z*wv.y; acc[2][2]+=av.z*wv.z; acc[2][3]+=av.z*wv.w;
      acc[3][0]+=av.w*wv.x; acc[3][1]+=av.w*wv.y; acc[3][2]+=av.w*wv.z; acc[3][3]+=av.w*wv.w;
    }
    __syncthreads();
  }

  float* T = pool;  // 64 x 65
#pragma unroll
  for(int i=0;i<4;i++){
#pragma unroll
    for(int j2=0;j2<4;j2++){
      int cc = ty*4+j2;
      T[(tx*4+i)*65 + cc] = acc[i][j2] + bias[((cc>>4)*512) + c*16 + (cc&15)];
    }
  }
  __syncthreads();

#pragma unroll
  for(int u=0;u<4;u++){
    int cell = tid + u*256;
    int r = cell>>4, jj = cell&15;
    float ig = sigm(T[r*65+jj]);
    float fg = sigm(T[r*65+16+jj]);
    float gg = tanhf(T[r*65+32+jj]);
    float og = sigm(T[r*65+48+jj]);
    int b = m0 + r, j = c*16 + jj;
    float cn = fg * d_c[b*HH+j] + ig * gg;
    float hn = og * tanhf(cn);
    d_c[b*HH+j] = cn; d_h[b*HH+j] = hn;
    if(store_enc) d_encout[((size_t)b*SS + t)*HH + j] = hn;
  }
}

// ---------------- TMA ring: issue one chunk (up to 8 rows x 2KB) ----------------
__device__ __forceinline__ void issue_chunk(const float* refbase, const int* sAl, int c, int n,
                                            uint32_t bufu32, uint32_t mb0){
  int bi = c & 3;
  int rows = n - c*8; if(rows > 8) rows = 8;
  uint32_t mb = mb0 + bi*8;
  MBEXPECT(mb, (uint32_t)(rows*2048));
#pragma unroll 1
  for(int r=0;r<rows;r++){
    const float* src = refbase + (size_t)sAl[c*8+r]*HH;
    uint32_t dst = bufu32 + bi*16384 + r*2048;
    BULK_G2S(dst, src, 2048u, mb);
  }
}

// ---------------- THE persistent mega-kernel ----------------
__global__ void __launch_bounds__(NTHR, 2)
pointer_net_kernel(const float* __restrict__ embedding,
                   const float* __restrict__ enc_Wih, const float* __restrict__ enc_Whh, const float* __restrict__ enc_b,
                   const float* __restrict__ dec_Wih, const float* __restrict__ dec_Whh, const float* __restrict__ dec_b,
                   const float* __restrict__ pt_Wq, const float* __restrict__ pt_bq,
                   const float* __restrict__ pt_Wref, const float* __restrict__ pt_bref, const float* __restrict__ pt_V,
                   const float* __restrict__ gl_Wq, const float* __restrict__ gl_bq,
                   const float* __restrict__ gl_Wref, const float* __restrict__ gl_bref, const float* __restrict__ gl_V,
                   const float* __restrict__ dec_start, const int* __restrict__ inputs,
                   float* __restrict__ out, int wr2)
{
  extern __shared__ __align__(128) unsigned char dynsm[];   // 64KB: 4 buffers x 8 rows x 2KB
  __shared__ __align__(16) float shPool[4160];
  __shared__ int shCities[64];
  __shared__ int s_alive[256];
  __shared__ __align__(8) unsigned long long s_mbar[4];
  __shared__ unsigned s_wm[8];
  __shared__ float s_scal[2];
  __shared__ int s_ptr;
  const int tid = threadIdx.x;
  const int bx  = blockIdx.x;
  const uint32_t bufu32 = s2u(dynsm);
  const uint32_t mb0 = s2u(s_mbar);

  // ---- init ----
  for(int i = bx*NTHR + tid; i < BB*HH; i += NBLK*NTHR){
    d_h[i] = 0.0f; d_c[i] = 0.0f;
    if(i < BB*SS)  d_alive[i] = i & (SS-1);
    if(i < BB*EE)  d_decin[i] = dec_start[i & (EE-1)];
  }
  if(tid==0){ for(int i=0;i<4;i++) MBINIT(mb0+i*8, 1); }
  gridsync();

  // ---- encoder ----
  for(int t=0;t<SS;t++){
    if(bx < 128) gates_lstm_tile(enc_Whh, enc_Wih, enc_b, embedding, inputs, t, 1, shPool, shCities);
    gridsync();
  }

  // ---- ref precompute ----
  for(int u = bx; u < 8192; u += NBLK)
    gemm_tile(d_encout, gl_Wref, gl_bref, d_glref, (long)(u>>3)*64, (u&7)*64, shPool, shPool+1088);
  for(int u = bx; u < 8192; u += NBLK)
    gemm_tile(d_encout, pt_Wref, pt_bref, d_ptref, (long)(u>>3)*64, (u&7)*64, shPool, shPool+1088);
  gridsync();

  // ---- decoder ----
  float* sq  = shPool;
  float* sV  = shPool + 512;
  float* sbf = shPool + 1024;
  float* sp  = shPool + 1280;
  float* red = shPool + 1536;
  int*  ridx = (int*)(shPool + 1792);
  const int w = tid>>5, l = tid&31;

  for(int t=0;t<SS;t++){
    const int n  = SS - t;
    const int nc = (n+7)>>3;
    if(bx < 128) gates_lstm_tile(dec_Whh, dec_Wih, dec_b, embedding, nullptr, t, 0, shPool, shCities);
    gridsync();
    if(bx < 128) gemm_tile32(d_h, gl_Wq, gl_bq, d_aq, (bx>>4)*32, (bx&15)*32, shPool, shPool+1152);
    gridsync();

    const int b = bx;
    const float* glbase = d_glref + (size_t)b*SS*HH;
    const float* ptbase = d_ptref + (size_t)b*SS*HH;

    // ======== GLIMPSE ========
    {
      s_alive[tid] = d_alive[b*SS + tid];
      sq[tid] = d_aq[b*HH + tid];   sq[tid+256] = d_aq[b*HH + tid + 256];
      sV[tid] = gl_V[tid];          sV[tid+256] = gl_V[tid+256];
      sbf[tid] = NEGINF;
      __syncthreads();
      if(tid==0){ for(int i=0;i<4;i++){ MBINVAL(mb0+i*8); MBINIT(mb0+i*8, 1); } }
      __syncthreads();
      // --- logits pipeline ---
      if(tid==0){ int pre = nc<4?nc:4; for(int c=0;c<pre;c++) issue_chunk(glbase, s_alive, c, n, bufu32, mb0); }
      for(int c=0;c<nc;c++){
        mbwait(mb0+(c&3)*8, (c>>2)&1);
        int ri = c*8 + w;
        if(ri < n){
          int s = s_alive[ri];
          const float* rp = (const float*)(dynsm + (size_t)(c&3)*16384 + (size_t)w*2048);
          float acc = 0.0f;
#pragma unroll
          for(int k=0;k<4;k++){
            int j = (k*32 + l)*4;
            float4 rv = *(const float4*)(rp + j);
            acc += tanhf(sq[j+0]+rv.x)*sV[j+0] + tanhf(sq[j+1]+rv.y)*sV[j+1]
                 + tanhf(sq[j+2]+rv.z)*sV[j+2] + tanhf(sq[j+3]+rv.w)*sV[j+3];
          }
          for(int off=16; off; off>>=1) acc += __shfl_down_sync(0xffffffffu, acc, off);
          if(l==0) sbf[s] = acc;
        }
        __syncthreads();
        if(tid==0 && c+4<nc) issue_chunk(glbase, s_alive, c+4, n, bufu32, mb0);
      }
      __syncthreads();
      // --- softmax (identical reductions) ---
      float x = sbf[tid];
      red[tid]=x; __syncthreads();
      for(int off=128; off; off>>=1){ if(tid<off) red[tid]=fmaxf(red[tid],red[tid+off]); __syncthreads(); }
      if(tid==0) s_scal[0]=red[0]; __syncthreads();
      float e = expf(x - s_scal[0]);
      red[tid]=e; __syncthreads();
      for(int off=128; off; off>>=1){ if(tid<off) red[tid]+=red[tid+off]; __syncthreads(); }
      if(tid==0) s_scal[1]=red[0]; __syncthreads();
      sp[tid] = e / s_scal[1];
      __syncthreads();
      // --- wsum pipeline (same rows, ascending order) ---
      if(tid==0){ for(int i=0;i<4;i++){ MBINVAL(mb0+i*8); MBINIT(mb0+i*8, 1); } }
      __syncthreads();
      if(tid==0){ int pre = nc<4?nc:4; for(int c=0;c<pre;c++) issue_chunk(glbase, s_alive, c, n, bufu32, mb0); }
      float acc0 = 0.0f, acc1 = 0.0f;
      for(int c=0;c<nc;c++){
        mbwait(mb0+(c&3)*8, (c>>2)&1);
        int rows = n - c*8; if(rows > 8) rows = 8;
        const float* bp = (const float*)(dynsm + (size_t)(c&3)*16384);
#pragma unroll 1
        for(int r=0;r<rows;r++){
          float pv = sp[s_alive[c*8+r]];
          acc0 += pv * bp[r*512 + tid];
          acc1 += pv * bp[r*512 + tid + 256];
        }
        __syncthreads();
        if(tid==0 && c+4<nc) issue_chunk(glbase, s_alive, c+4, n, bufu32, mb0);
      }
      d_qv[b*HH + tid]       = acc0;
      d_qv[b*HH + tid + 256] = acc1;
    }
    gridsync();
    if(bx < 128) gemm_tile32(d_qv, pt_Wq, pt_bq, d_ap, (bx>>4)*32, (bx&15)*32, shPool, shPool+1152);
    gridsync();

    // ======== POINTER + SAMPLE ========
    {
      sq[tid] = d_ap[b*HH + tid];   sq[tid+256] = d_ap[b*HH + tid + 256];
      sV[tid] = pt_V[tid];          sV[tid+256] = pt_V[tid+256];
      sbf[tid] = NEGINF;
      __syncthreads();
      if(tid==0){ for(int i=0;i<4;i++){ MBINVAL(mb0+i*8); MBINIT(mb0+i*8, 1); } }
      __syncthreads();
      if(tid==0){ int pre = nc<4?nc:4; for(int c=0;c<pre;c++) issue_chunk(ptbase, s_alive, c, n, bufu32, mb0); }
      for(int c=0;c<nc;c++){
        mbwait(mb0+(c&3)*8, (c>>2)&1);
        int ri = c*8 + w;
        if(ri < n){
          int s = s_alive[ri];
          const float* rp = (const float*)(dynsm + (size_t)(c&3)*16384 + (size_t)w*2048);
          float acc = 0.0f;
#pragma unroll
          for(int k=0;k<4;k++){
            int j = (k*32 + l)*4;
            float4 rv = *(const float4*)(rp + j);
            acc += tanhf(sq[j+0]+rv.x)*sV[j+0] + tanhf(sq[j+1]+rv.y)*sV[j+1]
                 + tanhf(sq[j+2]+rv.z)*sV[j+2] + tanhf(sq[j+3]+rv.w)*sV[j+3];
          }
          for(int off=16; off; off>>=1) acc += __shfl_down_sync(0xffffffffu, acc, off);
          if(l==0) sbf[s] = 10.0f * tanhf(acc);
        }
        __syncthreads();
        if(tid==0 && c+4<nc) issue_chunk(ptbase, s_alive, c+4, n, bufu32, mb0);
      }
      __syncthreads();
      float lg = sbf[tid];
      uint32_t a0u,a1u,o0,o1;
      tf2x32(0u, 1u, 0u, (uint32_t)t, a0u, a1u);
      tf2x32(a0u, a1u, 0u, (uint32_t)(b*SS+tid), o0, o1);
      uint32_t bits = o0 ^ o1;
      float u = __uint_as_float((bits>>9) | 0x3f800000u) - 1.0f;
      float gum = -logf(-logf(u + 1e-10f) + 1e-10f);
      float y = lg + gum;
      red[tid]=y; ridx[tid]=tid; __syncthreads();
      for(int off=128; off; off>>=1){
        if(tid<off){
          float v2f=red[tid+off]; int i2=ridx[tid+off];
          if(v2f>red[tid] || (v2f==red[tid] && i2<ridx[tid])){ red[tid]=v2f; ridx[tid]=i2; }
        }
        __syncthreads();
      }
      if(tid==0) s_ptr = ridx[0]; __syncthreads();
      red[tid]=lg; __syncthreads();
      for(int off=128; off; off>>=1){ if(tid<off) red[tid]=fmaxf(red[tid],red[tid+off]); __syncthreads(); }
      if(tid==0) s_scal[0]=red[0]; __syncthreads();
      red[tid]=expf(lg - s_scal[0]); __syncthreads();
      for(int off=128; off; off>>=1){ if(tid<off) red[tid]+=red[tid+off]; __syncthreads(); }
      if(tid==0) s_scal[1]=red[0]; __syncthreads();
      const int ptr = s_ptr;
      if(tid==0){
        float logp = sbf[ptr] - s_scal[0] - logf(s_scal[1]);
        out[b*SS + t] = (float)ptr;
        if(wr2) out[BB*SS + b*SS + t] = logp;
      }
      unsigned aliveb = (sbf[tid] > -1e8f) && (tid != ptr);
      unsigned wm = __ballot_sync(0xffffffffu, aliveb);
      if(l==0) s_wm[w] = wm;
      __syncthreads();
      int rank = __popc(wm & ((l==31)?0x7fffffffu:((1u<<l)-1u)));
      for(int ww=0; ww<w; ww++) rank += __popc(s_wm[ww]);
      if(aliveb) d_alive[b*SS + rank] = tid;
      if(tid < EE){
        int city = inputs[b*SS + ptr];
        d_decin[b*EE + tid] = embedding[city*EE + tid];
      }
    }
    gridsync();
  }
}

extern "C" void kernel_launch(void* const* d_in, const int* in_sizes, int n_in,
                              void* d_out, int out_size) {
  const float* embedding = (const float*)d_in[0];
  const float* enc_Wih   = (const float*)d_in[1];
  const float* enc_Whh   = (const float*)d_in[2];
  const float* enc_b     = (const float*)d_in[3];
  const float* dec_Wih   = (const float*)d_in[4];
  const float* dec_Whh   = (const float*)d_in[5];
  const float* dec_b     = (const float*)d_in[6];
  const float* pt_Wq     = (const float*)d_in[7];
  const float* pt_bq     = (const float*)d_in[8];
  const float* pt_Wref   = (const float*)d_in[9];
  const float* pt_bref   = (const float*)d_in[10];
  const float* pt_V      = (const float*)d_in[11];
  const float* gl_Wq     = (const float*)d_in[12];
  const float* gl_bq     = (const float*)d_in[13];
  const float* gl_Wref   = (const float*)d_in[14];
  const float* gl_bref   = (const float*)d_in[15];
  const float* gl_V      = (const float*)d_in[16];
  const float* dec_start = (const float*)d_in[17];
  const int*   inputs    = (const int*)d_in[18];
  float* out = (float*)d_out;
  int wr2 = (out_size >= 2*BB*SS) ? 1 : 0;

  cudaFuncSetAttribute(pointer_net_kernel, cudaFuncAttributeMaxDynamicSharedMemorySize, 65536);

  pointer_net_kernel<<<NBLK, NTHR, 65536>>>(embedding,
      enc_Wih, enc_Whh, enc_b, dec_Wih, dec_Whh, dec_b,
      pt_Wq, pt_bq, pt_Wref, pt_bref, pt_V,
      gl_Wq, gl_bq, gl_Wref, gl_bref, gl_V,
      dec_start, inputs, out, wr2);
}